// round 2
// baseline (speedup 1.0000x reference)
#include <cuda_runtime.h>
#include <math.h>

#define B 2
#define T 2048
#define H 16
#define DH 64
#define DIM 1024
#define M_TOTAL (B*T)   // 4096
#define ATT_SCALE 0.125f

// Scratch (device globals: allocation-free per harness rules)
__device__ float g_q [B*H*T*DH];
__device__ float g_k [B*H*T*DH];
__device__ float g_v [B*H*T*DH];
__device__ float g_ao[B*T*DIM];

// ---------------------------------------------------------------------------
// GEMM: C[m,n] = sum_k A[m,k] * W[n,k]   (A: M x K row-major, W: N x K row-major)
// mode 0: C row-major (M x N)
// mode 1: scatter n=(h*64+d), m=(b*T+t)  ->  C[((b*H+h)*T+t)*64 + d]
// ---------------------------------------------------------------------------
#define BM 128
#define BN 64
#define BK 16

__global__ __launch_bounds__(256) void gemm_nt(const float* __restrict__ A,
                                               const float* __restrict__ W,
                                               float* __restrict__ C, int mode)
{
    __shared__ float As[BK][BM + 4];
    __shared__ float Bs[BK][BN + 4];
    const int K = DIM, N = DIM;
    const int m0 = blockIdx.y * BM;
    const int n0 = blockIdx.x * BN;
    const int tid = threadIdx.x;
    const int tx = tid & 15;        // 16 col-groups of 4
    const int ty = tid >> 4;        // 16 row-groups of 8

    float acc[8][4];
    #pragma unroll
    for (int i = 0; i < 8; i++)
        #pragma unroll
        for (int j = 0; j < 4; j++) acc[i][j] = 0.f;

    for (int k0 = 0; k0 < K; k0 += BK) {
        // Load A tile (128x16) transposed into As[k][m]
        #pragma unroll
        for (int l = 0; l < 2; l++) {
            int idx = tid + l * 256;          // 0..511
            int r = idx >> 2;                 // 0..127
            int c4 = (idx & 3) * 4;           // 0,4,8,12
            float4 v = *(const float4*)(A + (size_t)(m0 + r) * K + k0 + c4);
            As[c4 + 0][r] = v.x; As[c4 + 1][r] = v.y;
            As[c4 + 2][r] = v.z; As[c4 + 3][r] = v.w;
        }
        // Load W tile (64x16) transposed into Bs[k][n]
        {
            int r = tid >> 2;                 // 0..63
            int c4 = (tid & 3) * 4;
            float4 v = *(const float4*)(W + (size_t)(n0 + r) * K + k0 + c4);
            Bs[c4 + 0][r] = v.x; Bs[c4 + 1][r] = v.y;
            Bs[c4 + 2][r] = v.z; Bs[c4 + 3][r] = v.w;
        }
        __syncthreads();

        #pragma unroll
        for (int k = 0; k < BK; k++) {
            float4 a0 = *(const float4*)&As[k][ty * 8];
            float4 a1 = *(const float4*)&As[k][ty * 8 + 4];
            float4 b0 = *(const float4*)&Bs[k][tx * 4];
            float a[8] = {a0.x, a0.y, a0.z, a0.w, a1.x, a1.y, a1.z, a1.w};
            float b[4] = {b0.x, b0.y, b0.z, b0.w};
            #pragma unroll
            for (int i = 0; i < 8; i++)
                #pragma unroll
                for (int j = 0; j < 4; j++)
                    acc[i][j] = fmaf(a[i], b[j], acc[i][j]);
        }
        __syncthreads();
    }

    if (mode == 0) {
        #pragma unroll
        for (int i = 0; i < 8; i++) {
            int m = m0 + ty * 8 + i;
            float4 v = make_float4(acc[i][0], acc[i][1], acc[i][2], acc[i][3]);
            *(float4*)(C + (size_t)m * N + n0 + tx * 4) = v;
        }
    } else {
        int h = n0 / DH;                 // BN == DH -> one head per block col
        int d = tx * 4;
        #pragma unroll
        for (int i = 0; i < 8; i++) {
            int m = m0 + ty * 8 + i;
            int bb = m / T, t = m % T;
            float4 v = make_float4(acc[i][0], acc[i][1], acc[i][2], acc[i][3]);
            *(float4*)(C + (((size_t)bb * H + h) * T + t) * DH + d) = v;
        }
    }
}

// ---------------------------------------------------------------------------
// RoPE (applied to Q and K in (b,h,t,d) layout)
// out[d]    = x[d]   *cos(p[d])    - x[d+32]*sin(p[d])        d in [0,32)
// out[d+32] = x[d+32]*cos(p[d+32]) + x[d]   *sin(p[d+32])
// ---------------------------------------------------------------------------
__global__ void rope_kernel(float* __restrict__ q, float* __restrict__ k,
                            const float* __restrict__ rope)
{
    int idx = blockIdx.x * blockDim.x + threadIdx.x;   // ((b*H+h)*T+t)*32 + d
    if (idx >= B * H * T * 32) return;
    int d    = idx & 31;
    int rest = idx >> 5;               // (b*H+h)*T + t
    int t    = rest & (T - 1);
    int bh   = rest >> 11;             // b*H + h
    int bidx = bh >> 4;                // b

    const float* pr = rope + ((size_t)bidx * T + t) * DH;
    float p1 = pr[d], p2 = pr[d + 32];
    float c1 = cosf(p1), s1 = sinf(p1);
    float c2 = cosf(p2), s2 = sinf(p2);

    size_t base = (size_t)rest * DH;
    float x1 = q[base + d], x2 = q[base + d + 32];
    q[base + d]      = x1 * c1 - x2 * s1;
    q[base + d + 32] = x2 * c2 + x1 * s2;
    float y1 = k[base + d], y2 = k[base + d + 32];
    k[base + d]      = y1 * c1 - y2 * s1;
    k[base + d + 32] = y2 * c2 + y1 * s2;
}

// ---------------------------------------------------------------------------
// Sliding-window causal attention.
// Block = (b, h, 64 queries). Keys needed: [q0-128, q0+63] -> 192 keys.
// Phase 1: load Q (transposed), K (transposed), V into smem
// Phase 2: S = Q K^T (register-tiled), mask + scale, store transposed S[k][q]
// Phase 3: softmax per query row (4 threads/row)
// Phase 4: O = P V (register-tiled), divide by row sum, write (b,t,h,d)
// ---------------------------------------------------------------------------
#define QT 64
#define KT 192
#define QS_P 68
#define KS_P 196
#define SS_P 68
#define VS_P 68
#define ATT_SMEM_FLOATS (64*QS_P + 64*KS_P + KT*SS_P + KT*VS_P + 64)

__global__ __launch_bounds__(256) void attn_kernel(const float* __restrict__ q,
                                                   const float* __restrict__ kk,
                                                   const float* __restrict__ vv,
                                                   float* __restrict__ out)
{
    extern __shared__ float sm[];
    float* Qs   = sm;                    // [64][QS_P]  Qs[d][q]
    float* Ks   = Qs + 64 * QS_P;        // [64][KS_P]  Ks[d][k]
    float* Ss   = Ks + 64 * KS_P;        // [KT][SS_P]  Ss[k][q]
    float* Vs   = Ss + KT * SS_P;        // [KT][VS_P]  Vs[k][d]
    float* rsum = Vs + KT * VS_P;        // [64]

    const int q0 = blockIdx.x * QT;
    const int h  = blockIdx.y;
    const int bb = blockIdx.z;
    const int tid = threadIdx.x;
    const size_t headbase = ((size_t)bb * H + h) * T * DH;
    const int k0 = q0 - 128;

    // ---- load Q transposed ----
    for (int idx = tid; idx < QT * 16; idx += 256) {
        int r = idx >> 4, c4 = (idx & 15) * 4;
        float4 v = *(const float4*)(q + headbase + (size_t)(q0 + r) * DH + c4);
        Qs[(c4 + 0) * QS_P + r] = v.x; Qs[(c4 + 1) * QS_P + r] = v.y;
        Qs[(c4 + 2) * QS_P + r] = v.z; Qs[(c4 + 3) * QS_P + r] = v.w;
    }
    // ---- load K transposed + V direct (clamped rows; mask fixes semantics) ----
    for (int idx = tid; idx < KT * 16; idx += 256) {
        int r = idx >> 4, c4 = (idx & 15) * 4;
        int kg = k0 + r;
        int kc = kg < 0 ? 0 : (kg >= T ? T - 1 : kg);
        float4 v = *(const float4*)(kk + headbase + (size_t)kc * DH + c4);
        Ks[(c4 + 0) * KS_P + r] = v.x; Ks[(c4 + 1) * KS_P + r] = v.y;
        Ks[(c4 + 2) * KS_P + r] = v.z; Ks[(c4 + 3) * KS_P + r] = v.w;
        float4 w = *(const float4*)(vv + headbase + (size_t)kc * DH + c4);
        *(float4*)(Vs + (size_t)r * VS_P + c4) = w;
    }
    __syncthreads();

    const int tx = tid & 15;   // 16 key-groups of 12
    const int ty = tid >> 4;   // 16 query-groups of 4

    // ---- phase 2: scores ----
    {
        float s[4][12];
        #pragma unroll
        for (int i = 0; i < 4; i++)
            #pragma unroll
            for (int j = 0; j < 12; j++) s[i][j] = 0.f;

        #pragma unroll 4
        for (int d = 0; d < 64; d++) {
            float4 qa  = *(const float4*)&Qs[d * QS_P + ty * 4];
            float4 kb0 = *(const float4*)&Ks[d * KS_P + tx * 12];
            float4 kb1 = *(const float4*)&Ks[d * KS_P + tx * 12 + 4];
            float4 kb2 = *(const float4*)&Ks[d * KS_P + tx * 12 + 8];
            float a[4] = {qa.x, qa.y, qa.z, qa.w};
            float b[12] = {kb0.x, kb0.y, kb0.z, kb0.w,
                           kb1.x, kb1.y, kb1.z, kb1.w,
                           kb2.x, kb2.y, kb2.z, kb2.w};
            #pragma unroll
            for (int i = 0; i < 4; i++)
                #pragma unroll
                for (int j = 0; j < 12; j++)
                    s[i][j] = fmaf(a[i], b[j], s[i][j]);
        }
        #pragma unroll
        for (int i = 0; i < 4; i++) {
            int qg = q0 + ty * 4 + i;
            #pragma unroll
            for (int j = 0; j < 12; j++) {
                int kl = tx * 12 + j;
                int kg = k0 + kl;
                bool valid = (kg >= 0) && (kg <= qg) && (kg >= qg - 128);
                Ss[kl * SS_P + ty * 4 + i] = valid ? s[i][j] * ATT_SCALE : -1e30f;
            }
        }
    }
    __syncthreads();

    // ---- phase 3: softmax (4 threads per query row) ----
    {
        int qr = tid >> 2, g = tid & 3;
        float m = -1e30f;
        for (int k = g; k < KT; k += 4) m = fmaxf(m, Ss[k * SS_P + qr]);
        m = fmaxf(m, __shfl_xor_sync(0xffffffffu, m, 1));
        m = fmaxf(m, __shfl_xor_sync(0xffffffffu, m, 2));
        float sum = 0.f;
        for (int k = g; k < KT; k += 4) {
            float e = __expf(Ss[k * SS_P + qr] - m);
            Ss[k * SS_P + qr] = e;
            sum += e;
        }
        sum += __shfl_xor_sync(0xffffffffu, sum, 1);
        sum += __shfl_xor_sync(0xffffffffu, sum, 2);
        if (g == 0) rsum[qr] = 1.0f / sum;
    }
    __syncthreads();

    // ---- phase 4: O = P V ----
    {
        float o[4][4];
        #pragma unroll
        for (int i = 0; i < 4; i++)
            #pragma unroll
            for (int j = 0; j < 4; j++) o[i][j] = 0.f;

        #pragma unroll 4
        for (int k = 0; k < KT; k++) {
            float4 p = *(const float4*)&Ss[k * SS_P + ty * 4];
            float4 v = *(const float4*)&Vs[k * VS_P + tx * 4];
            float pa[4] = {p.x, p.y, p.z, p.w};
            float vb[4] = {v.x, v.y, v.z, v.w};
            #pragma unroll
            for (int i = 0; i < 4; i++)
                #pragma unroll
                for (int j = 0; j < 4; j++)
                    o[i][j] = fmaf(pa[i], vb[j], o[i][j]);
        }
        #pragma unroll
        for (int i = 0; i < 4; i++) {
            int qg = q0 + ty * 4 + i;
            float r = rsum[ty * 4 + i];
            float4 v = make_float4(o[i][0] * r, o[i][1] * r, o[i][2] * r, o[i][3] * r);
            *(float4*)(out + (((size_t)bb * T + qg) * H + h) * DH + tx * 4) = v;
        }
    }
}

// ---------------------------------------------------------------------------
extern "C" void kernel_launch(void* const* d_in, const int* in_sizes, int n_in,
                              void* d_out, int out_size)
{
    const float* x    = (const float*)d_in[0];
    // d_in[1] = attention_mask (all ones in this problem; window+causal applied in-kernel)
    const float* rope = (const float*)d_in[2];
    const float* Wq   = (const float*)d_in[3];
    const float* Wk   = (const float*)d_in[4];
    const float* Wv   = (const float*)d_in[5];
    const float* Wo   = (const float*)d_in[6];
    float* out = (float*)d_out;

    float *q, *k, *v, *ao;
    cudaGetSymbolAddress((void**)&q,  g_q);
    cudaGetSymbolAddress((void**)&k,  g_k);
    cudaGetSymbolAddress((void**)&v,  g_v);
    cudaGetSymbolAddress((void**)&ao, g_ao);

    dim3 ggrid(DIM / BN, M_TOTAL / BM);   // (16, 32)
    gemm_nt<<<ggrid, 256>>>(x, Wq, q, 1);
    gemm_nt<<<ggrid, 256>>>(x, Wk, k, 1);
    gemm_nt<<<ggrid, 256>>>(x, Wv, v, 1);

    int nrope = B * H * T * 32;
    rope_kernel<<<(nrope + 255) / 256, 256>>>(q, k, rope);

    int smem_bytes = ATT_SMEM_FLOATS * (int)sizeof(float);
    cudaFuncSetAttribute(attn_kernel, cudaFuncAttributeMaxDynamicSharedMemorySize, smem_bytes);
    attn_kernel<<<dim3(T / QT, H, B), 256, smem_bytes>>>(q, k, v, ao);

    gemm_nt<<<ggrid, 256>>>(ao, Wo, out, 0);
}

// round 4
// speedup vs baseline: 2.0137x; 2.0137x over previous
#include <cuda_runtime.h>
#include <cuda_bf16.h>
#include <math.h>
#include <stdint.h>

#define B 2
#define T 2048
#define H 16
#define DH 64
#define DIM 1024
#define M_TOTAL (B*T)   // 4096
#define ATT_SCALE 0.125f

// ---------------- scratch (device globals; allocation-free) ----------------
__device__ float g_q [B*H*T*DH];
__device__ float g_k [B*H*T*DH];
__device__ float g_v [B*H*T*DH];
__device__ float g_ao[B*T*DIM];
__device__ __nv_bfloat16 g_xhi[M_TOTAL*DIM];
__device__ __nv_bfloat16 g_xlo[M_TOTAL*DIM];
__device__ __nv_bfloat16 g_whi[DIM*DIM];
__device__ __nv_bfloat16 g_wlo[DIM*DIM];

// ---------------- helpers ----------------
__device__ __forceinline__ uint32_t smem_u32(const void* p) {
    uint32_t a;
    asm("{ .reg .u64 t; cvta.to.shared.u64 t, %1; cvt.u32.u64 %0, t; }"
        : "=r"(a) : "l"(p));
    return a;
}

#define CP_ASYNC16(dst_u32, src_ptr) \
    asm volatile("cp.async.cg.shared.global [%0], [%1], 16;" :: "r"(dst_u32), "l"(src_ptr))
#define CP_COMMIT()  asm volatile("cp.async.commit_group;" ::: "memory")
#define CP_WAIT0()   asm volatile("cp.async.wait_group 0;" ::: "memory")
#define CP_WAIT1()   asm volatile("cp.async.wait_group 1;" ::: "memory")

__device__ __forceinline__ void mma_bf16(float* c, const uint32_t* a, const uint32_t* b) {
    asm volatile(
        "mma.sync.aligned.m16n8k16.row.col.f32.bf16.bf16.f32 "
        "{%0,%1,%2,%3}, {%4,%5,%6,%7}, {%8,%9}, {%0,%1,%2,%3};"
        : "+f"(c[0]), "+f"(c[1]), "+f"(c[2]), "+f"(c[3])
        : "r"(a[0]), "r"(a[1]), "r"(a[2]), "r"(a[3]), "r"(b[0]), "r"(b[1]));
}

// ---------------------------------------------------------------------------
// split fp32 -> bf16 hi + bf16 lo
// ---------------------------------------------------------------------------
__global__ void split_bf16(const float* __restrict__ x,
                           __nv_bfloat16* __restrict__ hi,
                           __nv_bfloat16* __restrict__ lo, int n4)
{
    int i = blockIdx.x * blockDim.x + threadIdx.x;
    if (i >= n4) return;
    float4 v = ((const float4*)x)[i];
    __nv_bfloat16 h0 = __float2bfloat16(v.x);
    __nv_bfloat16 h1 = __float2bfloat16(v.y);
    __nv_bfloat16 h2 = __float2bfloat16(v.z);
    __nv_bfloat16 h3 = __float2bfloat16(v.w);
    __nv_bfloat16 l0 = __float2bfloat16(v.x - __bfloat162float(h0));
    __nv_bfloat16 l1 = __float2bfloat16(v.y - __bfloat162float(h1));
    __nv_bfloat16 l2 = __float2bfloat16(v.z - __bfloat162float(h2));
    __nv_bfloat16 l3 = __float2bfloat16(v.w - __bfloat162float(h3));
    __nv_bfloat162* Hp = (__nv_bfloat162*)hi;
    __nv_bfloat162* Lp = (__nv_bfloat162*)lo;
    __nv_bfloat162 a, b2;
    a.x = h0; a.y = h1; b2.x = h2; b2.y = h3;
    Hp[2*i] = a; Hp[2*i+1] = b2;
    a.x = l0; a.y = l1; b2.x = l2; b2.y = l3;
    Lp[2*i] = a; Lp[2*i+1] = b2;
}

// ---------------------------------------------------------------------------
// Tensor-core GEMM (mma.sync m16n8k16 bf16, split precision):
//   C[m,n] = sum_k A[m,k] * W[n,k]   fp32-equivalent via Ah*Wh + Ah*Wl + Al*Wh
// CTA: 128x128 tile, 256 threads (8 warps of 64x32). BK=32, double-buffered
// cp.async. SMEM rows padded to 40 bf16 (conflict-free fragment gathers).
// mode 0: C row-major.  mode 1: scatter to (b,h,t,d).
// ---------------------------------------------------------------------------
#define BKC 32
#define RS  40                      // smem row stride in bf16 (80 bytes)
#define TILE_B (128*RS*2)           // 10240 bytes per 128x32 tile
#define BUF_B  (4*TILE_B)           // Ah, Al, Wh, Wl
#define GEMM_SMEM (2*BUF_B)         // 81920 bytes

__global__ __launch_bounds__(256) void gemm_mma(
    const __nv_bfloat16* __restrict__ Ahi, const __nv_bfloat16* __restrict__ Alo,
    const __nv_bfloat16* __restrict__ Whi, const __nv_bfloat16* __restrict__ Wlo,
    float* __restrict__ C, int mode)
{
    extern __shared__ __align__(16) char sm[];
    __nv_bfloat16* sb = (__nv_bfloat16*)sm;
    const uint32_t smb = smem_u32(sm);

    const int tid  = threadIdx.x;
    const int m0   = blockIdx.y * 128;
    const int n0   = blockIdx.x * 128;
    const int wid  = tid >> 5;
    const int lane = tid & 31;
    const int g    = lane >> 2;       // group id 0..7
    const int t2   = (lane & 3) * 2;  // 0,2,4,6
    const int wm   = (wid & 1) * 64;
    const int wn   = (wid >> 1) * 32;

    float acc[4][4][4];
    #pragma unroll
    for (int mt = 0; mt < 4; mt++)
        #pragma unroll
        for (int nt = 0; nt < 4; nt++)
            #pragma unroll
            for (int e = 0; e < 4; e++) acc[mt][nt][e] = 0.f;

    // async load of one K-chunk into buffer `buf`
    auto load_chunk = [&](int c, int buf) {
        const int k0 = c * BKC;
        const uint32_t bb = smb + (uint32_t)buf * BUF_B;
        #pragma unroll
        for (int i = 0; i < 8; i++) {
            int idx = tid + i * 256;      // 0..2047
            int arr = idx >> 9;           // 0..3
            int rem = idx & 511;
            int r   = rem >> 2;           // 0..127
            int c8  = (rem & 3) * 8;      // bf16 col within chunk
            const __nv_bfloat16* src;
            int rowbase;
            if (arr == 0)      { src = Ahi; rowbase = m0 + r; }
            else if (arr == 1) { src = Alo; rowbase = m0 + r; }
            else if (arr == 2) { src = Whi; rowbase = n0 + r; }
            else               { src = Wlo; rowbase = n0 + r; }
            uint32_t dst = bb + (uint32_t)arr * TILE_B + (uint32_t)(r * RS + c8) * 2;
            CP_ASYNC16(dst, src + (size_t)rowbase * DIM + k0 + c8);
        }
    };

    const int NC = DIM / BKC;   // 32
    load_chunk(0, 0);
    CP_COMMIT();

    for (int c = 0; c < NC; c++) {
        if (c + 1 < NC) {
            load_chunk(c + 1, (c + 1) & 1);
            CP_COMMIT();
            CP_WAIT1();
        } else {
            CP_WAIT0();
        }
        __syncthreads();

        const __nv_bfloat16* Ah_s = sb + ((size_t)(c & 1) * BUF_B) / 2;
        const __nv_bfloat16* Al_s = Ah_s + TILE_B / 2;
        const __nv_bfloat16* Wh_s = Al_s + TILE_B / 2;
        const __nv_bfloat16* Wl_s = Wh_s + TILE_B / 2;

        #pragma unroll
        for (int ks = 0; ks < 2; ks++) {
            const int kc = ks * 16 + t2;
            uint32_t ah[4][4], al[4][4], wh[4][2], wl[4][2];
            #pragma unroll
            for (int mt = 0; mt < 4; mt++) {
                int r0 = wm + mt * 16 + g;
                ah[mt][0] = *(const uint32_t*)(Ah_s + r0 * RS + kc);
                ah[mt][1] = *(const uint32_t*)(Ah_s + (r0 + 8) * RS + kc);
                ah[mt][2] = *(const uint32_t*)(Ah_s + r0 * RS + kc + 8);
                ah[mt][3] = *(const uint32_t*)(Ah_s + (r0 + 8) * RS + kc + 8);
                al[mt][0] = *(const uint32_t*)(Al_s + r0 * RS + kc);
                al[mt][1] = *(const uint32_t*)(Al_s + (r0 + 8) * RS + kc);
                al[mt][2] = *(const uint32_t*)(Al_s + r0 * RS + kc + 8);
                al[mt][3] = *(const uint32_t*)(Al_s + (r0 + 8) * RS + kc + 8);
            }
            #pragma unroll
            for (int nt = 0; nt < 4; nt++) {
                int rn = wn + nt * 8 + g;
                wh[nt][0] = *(const uint32_t*)(Wh_s + rn * RS + kc);
                wh[nt][1] = *(const uint32_t*)(Wh_s + rn * RS + kc + 8);
                wl[nt][0] = *(const uint32_t*)(Wl_s + rn * RS + kc);
                wl[nt][1] = *(const uint32_t*)(Wl_s + rn * RS + kc + 8);
            }
            #pragma unroll
            for (int mt = 0; mt < 4; mt++)
                #pragma unroll
                for (int nt = 0; nt < 4; nt++) {
                    mma_bf16(acc[mt][nt], ah[mt], wh[nt]);
                    mma_bf16(acc[mt][nt], ah[mt], wl[nt]);
                    mma_bf16(acc[mt][nt], al[mt], wh[nt]);
                }
        }
        __syncthreads();
    }

    // ---- epilogue ----
    #pragma unroll
    for (int mt = 0; mt < 4; mt++) {
        int row0 = m0 + wm + mt * 16 + g;
        #pragma unroll
        for (int nt = 0; nt < 4; nt++) {
            int col = n0 + wn + nt * 8 + t2;
            if (mode == 0) {
                float2 v0 = make_float2(acc[mt][nt][0], acc[mt][nt][1]);
                float2 v1 = make_float2(acc[mt][nt][2], acc[mt][nt][3]);
                *(float2*)(C + (size_t)row0 * DIM + col) = v0;
                *(float2*)(C + (size_t)(row0 + 8) * DIM + col) = v1;
            } else {
                int h = col >> 6, d = col & 63;
                int bb0 = row0 >> 11, t0 = row0 & (T - 1);
                int bb1 = (row0 + 8) >> 11, t1 = (row0 + 8) & (T - 1);
                float2 v0 = make_float2(acc[mt][nt][0], acc[mt][nt][1]);
                float2 v1 = make_float2(acc[mt][nt][2], acc[mt][nt][3]);
                *(float2*)(C + (((size_t)bb0 * H + h) * T + t0) * DH + d) = v0;
                *(float2*)(C + (((size_t)bb1 * H + h) * T + t1) * DH + d) = v1;
            }
        }
    }
}

// ---------------------------------------------------------------------------
// RoPE (applied to Q and K in (b,h,t,d) layout)
// ---------------------------------------------------------------------------
__global__ void rope_kernel(float* __restrict__ q, float* __restrict__ k,
                            const float* __restrict__ rope)
{
    int idx = blockIdx.x * blockDim.x + threadIdx.x;   // ((b*H+h)*T+t)*32 + d
    if (idx >= B * H * T * 32) return;
    int d    = idx & 31;
    int rest = idx >> 5;               // (b*H+h)*T + t
    int t    = rest & (T - 1);
    int bh   = rest >> 11;             // b*H + h
    int bidx = bh >> 4;                // b

    const float* pr = rope + ((size_t)bidx * T + t) * DH;
    float p1 = pr[d], p2 = pr[d + 32];
    float c1 = cosf(p1), s1 = sinf(p1);
    float c2 = cosf(p2), s2 = sinf(p2);

    size_t base = (size_t)rest * DH;
    float x1 = q[base + d], x2 = q[base + d + 32];
    q[base + d]      = x1 * c1 - x2 * s1;
    q[base + d + 32] = x2 * c2 + x1 * s2;
    float y1 = k[base + d], y2 = k[base + d + 32];
    k[base + d]      = y1 * c1 - y2 * s1;
    k[base + d + 32] = y2 * c2 + y1 * s2;
}

// ---------------------------------------------------------------------------
// Sliding-window causal attention (fp32; known-good from R2)
// ---------------------------------------------------------------------------
#define QT 64
#define KT 192
#define QS_P 68
#define KS_P 196
#define SS_P 68
#define VS_P 68
#define ATT_SMEM_FLOATS (64*QS_P + 64*KS_P + KT*SS_P + KT*VS_P + 64)

__global__ __launch_bounds__(256) void attn_kernel(const float* __restrict__ q,
                                                   const float* __restrict__ kk,
                                                   const float* __restrict__ vv,
                                                   float* __restrict__ out)
{
    extern __shared__ float smf[];
    float* Qs   = smf;
    float* Ks   = Qs + 64 * QS_P;
    float* Ss   = Ks + 64 * KS_P;
    float* Vs   = Ss + KT * SS_P;
    float* rsum = Vs + KT * VS_P;

    const int q0 = blockIdx.x * QT;
    const int h  = blockIdx.y;
    const int bb = blockIdx.z;
    const int tid = threadIdx.x;
    const size_t headbase = ((size_t)bb * H + h) * T * DH;
    const int k0 = q0 - 128;

    for (int idx = tid; idx < QT * 16; idx += 256) {
        int r = idx >> 4, c4 = (idx & 15) * 4;
        float4 v = *(const float4*)(q + headbase + (size_t)(q0 + r) * DH + c4);
        Qs[(c4 + 0) * QS_P + r] = v.x; Qs[(c4 + 1) * QS_P + r] = v.y;
        Qs[(c4 + 2) * QS_P + r] = v.z; Qs[(c4 + 3) * QS_P + r] = v.w;
    }
    for (int idx = tid; idx < KT * 16; idx += 256) {
        int r = idx >> 4, c4 = (idx & 15) * 4;
        int kg = k0 + r;
        int kc = kg < 0 ? 0 : (kg >= T ? T - 1 : kg);
        float4 v = *(const float4*)(kk + headbase + (size_t)kc * DH + c4);
        Ks[(c4 + 0) * KS_P + r] = v.x; Ks[(c4 + 1) * KS_P + r] = v.y;
        Ks[(c4 + 2) * KS_P + r] = v.z; Ks[(c4 + 3) * KS_P + r] = v.w;
        float4 w = *(const float4*)(vv + headbase + (size_t)kc * DH + c4);
        *(float4*)(Vs + (size_t)r * VS_P + c4) = w;
    }
    __syncthreads();

    const int tx = tid & 15;
    const int ty = tid >> 4;

    {
        float s[4][12];
        #pragma unroll
        for (int i = 0; i < 4; i++)
            #pragma unroll
            for (int j = 0; j < 12; j++) s[i][j] = 0.f;

        #pragma unroll 4
        for (int d = 0; d < 64; d++) {
            float4 qa  = *(const float4*)&Qs[d * QS_P + ty * 4];
            float4 kb0 = *(const float4*)&Ks[d * KS_P + tx * 12];
            float4 kb1 = *(const float4*)&Ks[d * KS_P + tx * 12 + 4];
            float4 kb2 = *(const float4*)&Ks[d * KS_P + tx * 12 + 8];
            float a[4] = {qa.x, qa.y, qa.z, qa.w};
            float b[12] = {kb0.x, kb0.y, kb0.z, kb0.w,
                           kb1.x, kb1.y, kb1.z, kb1.w,
                           kb2.x, kb2.y, kb2.z, kb2.w};
            #pragma unroll
            for (int i = 0; i < 4; i++)
                #pragma unroll
                for (int j = 0; j < 12; j++)
                    s[i][j] = fmaf(a[i], b[j], s[i][j]);
        }
        #pragma unroll
        for (int i = 0; i < 4; i++) {
            int qg = q0 + ty * 4 + i;
            #pragma unroll
            for (int j = 0; j < 12; j++) {
                int kl = tx * 12 + j;
                int kg = k0 + kl;
                bool valid = (kg >= 0) && (kg <= qg) && (kg >= qg - 128);
                Ss[kl * SS_P + ty * 4 + i] = valid ? s[i][j] * ATT_SCALE : -1e30f;
            }
        }
    }
    __syncthreads();

    {
        int qr = tid >> 2, gq = tid & 3;
        float m = -1e30f;
        for (int k = gq; k < KT; k += 4) m = fmaxf(m, Ss[k * SS_P + qr]);
        m = fmaxf(m, __shfl_xor_sync(0xffffffffu, m, 1));
        m = fmaxf(m, __shfl_xor_sync(0xffffffffu, m, 2));
        float sum = 0.f;
        for (int k = gq; k < KT; k += 4) {
            float e = __expf(Ss[k * SS_P + qr] - m);
            Ss[k * SS_P + qr] = e;
            sum += e;
        }
        sum += __shfl_xor_sync(0xffffffffu, sum, 1);
        sum += __shfl_xor_sync(0xffffffffu, sum, 2);
        if (gq == 0) rsum[qr] = 1.0f / sum;
    }
    __syncthreads();

    {
        float o[4][4];
        #pragma unroll
        for (int i = 0; i < 4; i++)
            #pragma unroll
            for (int j = 0; j < 4; j++) o[i][j] = 0.f;

        #pragma unroll 4
        for (int k = 0; k < KT; k++) {
            float4 p = *(const float4*)&Ss[k * SS_P + ty * 4];
            float4 v = *(const float4*)&Vs[k * VS_P + tx * 4];
            float pa[4] = {p.x, p.y, p.z, p.w};
            float vb[4] = {v.x, v.y, v.z, v.w};
            #pragma unroll
            for (int i = 0; i < 4; i++)
                #pragma unroll
                for (int j = 0; j < 4; j++)
                    o[i][j] = fmaf(pa[i], vb[j], o[i][j]);
        }
        #pragma unroll
        for (int i = 0; i < 4; i++) {
            int qg = q0 + ty * 4 + i;
            float r = rsum[ty * 4 + i];
            float4 v = make_float4(o[i][0] * r, o[i][1] * r, o[i][2] * r, o[i][3] * r);
            *(float4*)(out + (((size_t)bb * T + qg) * H + h) * DH + tx * 4) = v;
        }
    }
}

// ---------------------------------------------------------------------------
extern "C" void kernel_launch(void* const* d_in, const int* in_sizes, int n_in,
                              void* d_out, int out_size)
{
    const float* x    = (const float*)d_in[0];
    // d_in[1] = attention_mask (all ones; window+causal handled in-kernel)
    const float* rope = (const float*)d_in[2];
    const float* Wq   = (const float*)d_in[3];
    const float* Wk   = (const float*)d_in[4];
    const float* Wv   = (const float*)d_in[5];
    const float* Wo   = (const float*)d_in[6];
    float* out = (float*)d_out;

    float *q, *k, *v, *ao;
    __nv_bfloat16 *xhi, *xlo, *whi, *wlo;
    cudaGetSymbolAddress((void**)&q,   g_q);
    cudaGetSymbolAddress((void**)&k,   g_k);
    cudaGetSymbolAddress((void**)&v,   g_v);
    cudaGetSymbolAddress((void**)&ao,  g_ao);
    cudaGetSymbolAddress((void**)&xhi, g_xhi);
    cudaGetSymbolAddress((void**)&xlo, g_xlo);
    cudaGetSymbolAddress((void**)&whi, g_whi);
    cudaGetSymbolAddress((void**)&wlo, g_wlo);

    cudaFuncSetAttribute(gemm_mma, cudaFuncAttributeMaxDynamicSharedMemorySize, GEMM_SMEM);
    int att_smem = ATT_SMEM_FLOATS * (int)sizeof(float);
    cudaFuncSetAttribute(attn_kernel, cudaFuncAttributeMaxDynamicSharedMemorySize, att_smem);

    const int xn4 = M_TOTAL * DIM / 4;
    const int wn4 = DIM * DIM / 4;
    dim3 ggrid(DIM / 128, M_TOTAL / 128);   // (8, 32)

    split_bf16<<<xn4 / 256, 256>>>(x, xhi, xlo, xn4);

    split_bf16<<<wn4 / 256, 256>>>(Wq, whi, wlo, wn4);
    gemm_mma<<<ggrid, 256, GEMM_SMEM>>>(xhi, xlo, whi, wlo, q, 1);
    split_bf16<<<wn4 / 256, 256>>>(Wk, whi, wlo, wn4);
    gemm_mma<<<ggrid, 256, GEMM_SMEM>>>(xhi, xlo, whi, wlo, k, 1);
    split_bf16<<<wn4 / 256, 256>>>(Wv, whi, wlo, wn4);
    gemm_mma<<<ggrid, 256, GEMM_SMEM>>>(xhi, xlo, whi, wlo, v, 1);

    int nrope = B * H * T * 32;
    rope_kernel<<<(nrope + 255) / 256, 256>>>(q, k, rope);

    attn_kernel<<<dim3(T / QT, H, B), 256, att_smem>>>(q, k, v, ao);

    split_bf16<<<xn4 / 256, 256>>>(ao, xhi, xlo, xn4);
    split_bf16<<<wn4 / 256, 256>>>(Wo, whi, wlo, wn4);
    gemm_mma<<<ggrid, 256, GEMM_SMEM>>>(xhi, xlo, whi, wlo, out, 0);
}

// round 5
// speedup vs baseline: 2.2761x; 1.1303x over previous
#include <cuda_runtime.h>
#include <cuda_bf16.h>
#include <math.h>
#include <stdint.h>

#define B 2
#define T 2048
#define H 16
#define DH 64
#define DIM 1024
#define M_TOTAL (B*T)   // 4096
#define ATT_SCALE 0.125f

// ---------------- scratch (device globals; allocation-free) ----------------
__device__ float g_q [B*H*T*DH];
__device__ float g_k [B*H*T*DH];
__device__ float g_v [B*H*T*DH];
__device__ float g_ao[B*T*DIM];
__device__ __nv_bfloat16 g_xhi[M_TOTAL*DIM];
__device__ __nv_bfloat16 g_xlo[M_TOTAL*DIM];
__device__ __nv_bfloat16 g_whi[4*DIM*DIM];
__device__ __nv_bfloat16 g_wlo[4*DIM*DIM];

// ---------------- helpers ----------------
__device__ __forceinline__ uint32_t smem_u32(const void* p) {
    uint32_t a;
    asm("{ .reg .u64 t; cvta.to.shared.u64 t, %1; cvt.u32.u64 %0, t; }"
        : "=r"(a) : "l"(p));
    return a;
}

#define CP_ASYNC16(dst_u32, src_ptr) \
    asm volatile("cp.async.cg.shared.global [%0], [%1], 16;" :: "r"(dst_u32), "l"(src_ptr))
#define CP_COMMIT()  asm volatile("cp.async.commit_group;" ::: "memory")
#define CP_WAIT0()   asm volatile("cp.async.wait_group 0;" ::: "memory")
#define CP_WAIT1()   asm volatile("cp.async.wait_group 1;" ::: "memory")

#define LDM_X4(r0,r1,r2,r3, addr) \
    asm volatile("ldmatrix.sync.aligned.m8n8.x4.shared.b16 {%0,%1,%2,%3}, [%4];" \
                 : "=r"(r0), "=r"(r1), "=r"(r2), "=r"(r3) : "r"(addr))
#define LDM_X4_T(r0,r1,r2,r3, addr) \
    asm volatile("ldmatrix.sync.aligned.m8n8.x4.trans.shared.b16 {%0,%1,%2,%3}, [%4];" \
                 : "=r"(r0), "=r"(r1), "=r"(r2), "=r"(r3) : "r"(addr))

__device__ __forceinline__ void mma_bf16(float* c, const uint32_t* a, const uint32_t* b) {
    asm volatile(
        "mma.sync.aligned.m16n8k16.row.col.f32.bf16.bf16.f32 "
        "{%0,%1,%2,%3}, {%4,%5,%6,%7}, {%8,%9}, {%0,%1,%2,%3};"
        : "+f"(c[0]), "+f"(c[1]), "+f"(c[2]), "+f"(c[3])
        : "r"(a[0]), "r"(a[1]), "r"(a[2]), "r"(a[3]), "r"(b[0]), "r"(b[1]));
}

__device__ __forceinline__ uint32_t pk2(float a, float b) {
    __nv_bfloat162 t = __floats2bfloat162_rn(a, b);
    return *(uint32_t*)&t;
}

// ---------------------------------------------------------------------------
// split fp32 -> bf16 hi + bf16 lo
// ---------------------------------------------------------------------------
__global__ void split_bf16(const float* __restrict__ x,
                           __nv_bfloat16* __restrict__ hi,
                           __nv_bfloat16* __restrict__ lo, int n4)
{
    int i = blockIdx.x * blockDim.x + threadIdx.x;
    if (i >= n4) return;
    float4 v = ((const float4*)x)[i];
    __nv_bfloat16 h0 = __float2bfloat16(v.x);
    __nv_bfloat16 h1 = __float2bfloat16(v.y);
    __nv_bfloat16 h2 = __float2bfloat16(v.z);
    __nv_bfloat16 h3 = __float2bfloat16(v.w);
    __nv_bfloat16 l0 = __float2bfloat16(v.x - __bfloat162float(h0));
    __nv_bfloat16 l1 = __float2bfloat16(v.y - __bfloat162float(h1));
    __nv_bfloat16 l2 = __float2bfloat16(v.z - __bfloat162float(h2));
    __nv_bfloat16 l3 = __float2bfloat16(v.w - __bfloat162float(h3));
    __nv_bfloat162* Hp = (__nv_bfloat162*)hi;
    __nv_bfloat162* Lp = (__nv_bfloat162*)lo;
    __nv_bfloat162 a, b2;
    a.x = h0; a.y = h1; b2.x = h2; b2.y = h3;
    Hp[2*i] = a; Hp[2*i+1] = b2;
    a.x = l0; a.y = l1; b2.x = l2; b2.y = l3;
    Lp[2*i] = a; Lp[2*i+1] = b2;
}

// ---------------------------------------------------------------------------
// Tensor-core GEMM (split bf16, ldmatrix fragments)
//   C[m,n] = sum_k A[m,k]*W[n,k]
// mode 0: write Cq row-major (N=DIM, grid.x=8)
// mode 1: QKV fused (grid.x=24): which = n0>>10 selects Cq/Ck/Cv, scatter (b,h,t,d)
// ---------------------------------------------------------------------------
#define BKC 32
#define RS  40                      // smem row stride in bf16
#define TILE_B (128*RS*2)           // 10240 bytes per 128x32 tile
#define BUF_B  (4*TILE_B)
#define GEMM_SMEM (2*BUF_B)         // 81920 bytes

__global__ __launch_bounds__(256) void gemm_mma(
    const __nv_bfloat16* __restrict__ Ahi, const __nv_bfloat16* __restrict__ Alo,
    const __nv_bfloat16* __restrict__ Whi, const __nv_bfloat16* __restrict__ Wlo,
    float* __restrict__ Cq, float* __restrict__ Ck, float* __restrict__ Cv,
    int mode)
{
    extern __shared__ __align__(16) char sm[];
    const uint32_t smb = smem_u32(sm);

    const int tid  = threadIdx.x;
    const int m0   = blockIdx.y * 128;
    const int n0   = blockIdx.x * 128;     // global n (over up to 3072)
    const int wid  = tid >> 5;
    const int lane = tid & 31;
    const int g    = lane >> 2;
    const int t2   = (lane & 3) * 2;
    const int wm   = (wid & 1) * 64;
    const int wn   = (wid >> 1) * 32;

    float acc[4][4][4];
    #pragma unroll
    for (int mt = 0; mt < 4; mt++)
        #pragma unroll
        for (int nt = 0; nt < 4; nt++)
            #pragma unroll
            for (int e = 0; e < 4; e++) acc[mt][nt][e] = 0.f;

    auto load_chunk = [&](int c, int buf) {
        const int k0 = c * BKC;
        const uint32_t bb = smb + (uint32_t)buf * BUF_B;
        #pragma unroll
        for (int i = 0; i < 8; i++) {
            int idx = tid + i * 256;
            int arr = idx >> 9;
            int rem = idx & 511;
            int r   = rem >> 2;
            int c8  = (rem & 3) * 8;
            const __nv_bfloat16* src;
            int rowbase;
            if (arr == 0)      { src = Ahi; rowbase = m0 + r; }
            else if (arr == 1) { src = Alo; rowbase = m0 + r; }
            else if (arr == 2) { src = Whi; rowbase = n0 + r; }
            else               { src = Wlo; rowbase = n0 + r; }
            uint32_t dst = bb + (uint32_t)arr * TILE_B + (uint32_t)(r * RS + c8) * 2;
            CP_ASYNC16(dst, src + (size_t)rowbase * DIM + k0 + c8);
        }
    };

    // per-lane ldmatrix address offsets (halves) within a tile
    const uint32_t a_off = (uint32_t)((wm + (lane & 15)) * RS + ((lane & 16) ? 8 : 0));
    const uint32_t b_off = (uint32_t)((wn + (lane & 7) + ((lane & 16) ? 8 : 0)) * RS
                                      + ((lane & 8) ? 8 : 0));

    const int NC = DIM / BKC;   // 32
    load_chunk(0, 0);
    CP_COMMIT();

    for (int c = 0; c < NC; c++) {
        if (c + 1 < NC) {
            load_chunk(c + 1, (c + 1) & 1);
            CP_COMMIT();
            CP_WAIT1();
        } else {
            CP_WAIT0();
        }
        __syncthreads();

        const uint32_t base = smb + (uint32_t)(c & 1) * BUF_B;

        #pragma unroll
        for (int ks = 0; ks < 2; ks++) {
            const uint32_t kc = (uint32_t)(ks * 16);
            uint32_t ah[4][4], al[4][4], wh[2][4], wl[2][4];
            #pragma unroll
            for (int mt = 0; mt < 4; mt++) {
                uint32_t addr = base + (a_off + (uint32_t)(mt * 16) * RS + kc) * 2;
                LDM_X4(ah[mt][0], ah[mt][1], ah[mt][2], ah[mt][3], addr);
                LDM_X4(al[mt][0], al[mt][1], al[mt][2], al[mt][3], addr + TILE_B);
            }
            #pragma unroll
            for (int p = 0; p < 2; p++) {
                uint32_t addr = base + 2*TILE_B + (b_off + (uint32_t)(p * 16) * RS + kc) * 2;
                LDM_X4(wh[p][0], wh[p][1], wh[p][2], wh[p][3], addr);
                LDM_X4(wl[p][0], wl[p][1], wl[p][2], wl[p][3], addr + TILE_B);
            }
            #pragma unroll
            for (int mt = 0; mt < 4; mt++)
                #pragma unroll
                for (int nt = 0; nt < 4; nt++) {
                    uint32_t bh[2] = { wh[nt>>1][(nt&1)*2], wh[nt>>1][(nt&1)*2+1] };
                    uint32_t bl[2] = { wl[nt>>1][(nt&1)*2], wl[nt>>1][(nt&1)*2+1] };
                    mma_bf16(acc[mt][nt], ah[mt], bh);
                    mma_bf16(acc[mt][nt], ah[mt], bl);
                    mma_bf16(acc[mt][nt], al[mt], bh);
                }
        }
        __syncthreads();
    }

    // ---- epilogue ----
    float* C = Cq;
    int n0w = n0;
    if (mode == 1) {
        int which = n0 >> 10;
        C = (which == 0) ? Cq : (which == 1) ? Ck : Cv;
        n0w = n0 & 1023;
    }
    #pragma unroll
    for (int mt = 0; mt < 4; mt++) {
        int row0 = m0 + wm + mt * 16 + g;
        #pragma unroll
        for (int nt = 0; nt < 4; nt++) {
            int col = n0w + wn + nt * 8 + t2;
            float2 v0 = make_float2(acc[mt][nt][0], acc[mt][nt][1]);
            float2 v1 = make_float2(acc[mt][nt][2], acc[mt][nt][3]);
            if (mode == 0) {
                *(float2*)(C + (size_t)row0 * DIM + col) = v0;
                *(float2*)(C + (size_t)(row0 + 8) * DIM + col) = v1;
            } else {
                int h = col >> 6, d = col & 63;
                int bb0 = row0 >> 11, t0 = row0 & (T - 1);
                int bb1 = (row0 + 8) >> 11, t1 = (row0 + 8) & (T - 1);
                *(float2*)(C + (((size_t)bb0 * H + h) * T + t0) * DH + d) = v0;
                *(float2*)(C + (((size_t)bb1 * H + h) * T + t1) * DH + d) = v1;
            }
        }
    }
}

// ---------------------------------------------------------------------------
// RoPE
// ---------------------------------------------------------------------------
__global__ void rope_kernel(float* __restrict__ q, float* __restrict__ k,
                            const float* __restrict__ rope)
{
    int idx = blockIdx.x * blockDim.x + threadIdx.x;
    if (idx >= B * H * T * 32) return;
    int d    = idx & 31;
    int rest = idx >> 5;
    int t    = rest & (T - 1);
    int bh   = rest >> 11;
    int bidx = bh >> 4;

    const float* pr = rope + ((size_t)bidx * T + t) * DH;
    float p1 = pr[d], p2 = pr[d + 32];
    float c1 = cosf(p1), s1 = sinf(p1);
    float c2 = cosf(p2), s2 = sinf(p2);

    size_t base = (size_t)rest * DH;
    float x1 = q[base + d], x2 = q[base + d + 32];
    q[base + d]      = x1 * c1 - x2 * s1;
    q[base + d + 32] = x2 * c2 + x1 * s2;
    float y1 = k[base + d], y2 = k[base + d + 32];
    k[base + d]      = y1 * c1 - y2 * s1;
    k[base + d + 32] = y2 * c2 + y1 * s2;
}

// ---------------------------------------------------------------------------
// Tensor-core sliding-window attention.
// Block = (64 queries, h, b); keys [q0-128, q0+63] -> 192.
// Q/K/V converted to bf16 hi/lo in smem (stride 72 b16, conflict-free ldmatrix).
// 8 warps: mt = w&3 (16 q-rows), half = w>>2 (96 keys).
// S via 3-pass split mma; full softmax (cross-half via smem); P split at pack;
// PV via 3-pass split mma with ldmatrix.trans on V; halves combined via smem.
// ---------------------------------------------------------------------------
#define ARS 72                       // attn smem row stride (b16)
#define AQH 0
#define AQL (64*ARS*2)               // 9216
#define AKH (2*64*ARS*2)             // 18432
#define AKL (AKH + 192*ARS*2)
#define AVH (AKL + 192*ARS*2)
#define AVL (AVH + 192*ARS*2)
#define ARED (AVL + 192*ARS*2)       // 129024
#define ATT_SMEM (ARED + 1024)       // 130048 bytes
// scratch for half-combine reuses [AQH, AQH+16KB)

__global__ __launch_bounds__(256) void attn_mma(const float* __restrict__ q,
                                                const float* __restrict__ kk,
                                                const float* __restrict__ vv,
                                                float* __restrict__ out)
{
    extern __shared__ __align__(16) char sm[];
    const uint32_t smb = smem_u32(sm);
    float* redm = (float*)(sm + ARED);          // [2][64]
    float* reds = (float*)(sm + ARED + 512);    // [2][64]
    float* scratch = (float*)sm;                // 4096 floats

    const int q0 = blockIdx.x * 64;
    const int h  = blockIdx.y;
    const int bb = blockIdx.z;
    const int tid = threadIdx.x;
    const int wid = tid >> 5;
    const int lane = tid & 31;
    const size_t headbase = ((size_t)bb * H + h) * T * DH;
    const int k0 = q0 - 128;

    // ---- load & split Q (64x64), K (192x64), V (192x64) ----
    {
        // Q: 1024 float4
        #pragma unroll
        for (int i = 0; i < 4; i++) {
            int idx = tid + i * 256;
            int r = idx >> 4, c4 = (idx & 15) * 4;
            float4 v = *(const float4*)(q + headbase + (size_t)(q0 + r) * DH + c4);
            __nv_bfloat16* Hs = (__nv_bfloat16*)(sm + AQH) + r * ARS + c4;
            __nv_bfloat16* Ls = (__nv_bfloat16*)(sm + AQL) + r * ARS + c4;
            float f[4] = {v.x, v.y, v.z, v.w};
            #pragma unroll
            for (int e = 0; e < 4; e++) {
                __nv_bfloat16 hb = __float2bfloat16(f[e]);
                Hs[e] = hb;
                Ls[e] = __float2bfloat16(f[e] - __bfloat162float(hb));
            }
        }
        // K and V: 3072 float4 each
        #pragma unroll
        for (int i = 0; i < 12; i++) {
            int idx = tid + i * 256;
            int r = idx >> 4, c4 = (idx & 15) * 4;
            int kg = k0 + r;
            int kc = kg < 0 ? 0 : (kg >= T ? T - 1 : kg);
            float4 v = *(const float4*)(kk + headbase + (size_t)kc * DH + c4);
            float4 w = *(const float4*)(vv + headbase + (size_t)kc * DH + c4);
            __nv_bfloat16* KH = (__nv_bfloat16*)(sm + AKH) + r * ARS + c4;
            __nv_bfloat16* KL = (__nv_bfloat16*)(sm + AKL) + r * ARS + c4;
            __nv_bfloat16* VH = (__nv_bfloat16*)(sm + AVH) + r * ARS + c4;
            __nv_bfloat16* VL = (__nv_bfloat16*)(sm + AVL) + r * ARS + c4;
            float fk[4] = {v.x, v.y, v.z, v.w};
            float fv[4] = {w.x, w.y, w.z, w.w};
            #pragma unroll
            for (int e = 0; e < 4; e++) {
                __nv_bfloat16 hb = __float2bfloat16(fk[e]);
                KH[e] = hb; KL[e] = __float2bfloat16(fk[e] - __bfloat162float(hb));
                __nv_bfloat16 vb = __float2bfloat16(fv[e]);
                VH[e] = vb; VL[e] = __float2bfloat16(fv[e] - __bfloat162float(vb));
            }
        }
    }
    __syncthreads();

    const int mt   = wid & 3;
    const int half = wid >> 2;
    const int row_r = lane >> 2;

    // ---- S = Q K^T (split, 3 passes) ----
    float p[12][4];
    #pragma unroll
    for (int nt = 0; nt < 12; nt++)
        #pragma unroll
        for (int e = 0; e < 4; e++) p[nt][e] = 0.f;

    const uint32_t qa_off = (uint32_t)((mt * 16 + (lane & 15)) * ARS
                                       + ((lane & 16) ? 8 : 0)) * 2;
    const uint32_t kb_row = (uint32_t)(half * 96 + (lane & 7) + ((lane & 16) ? 8 : 0));
    const uint32_t kb_coff = (uint32_t)((lane & 8) ? 8 : 0);

    #pragma unroll
    for (int kt = 0; kt < 4; kt++) {
        const uint32_t kc = (uint32_t)(kt * 16);
        uint32_t aq_h[4], aq_l[4];
        {
            uint32_t addr = smb + AQH + qa_off + kc * 2;
            LDM_X4(aq_h[0], aq_h[1], aq_h[2], aq_h[3], addr);
            LDM_X4(aq_l[0], aq_l[1], aq_l[2], aq_l[3], addr + (AQL - AQH));
        }
        #pragma unroll
        for (int pp = 0; pp < 6; pp++) {
            uint32_t addr = smb + AKH
                + ((kb_row + (uint32_t)(pp * 16)) * ARS + kc + kb_coff) * 2;
            uint32_t bh[4], bl[4];
            LDM_X4(bh[0], bh[1], bh[2], bh[3], addr);
            LDM_X4(bl[0], bl[1], bl[2], bl[3], addr + (AKL - AKH));
            #pragma unroll
            for (int sub = 0; sub < 2; sub++) {
                int nt = pp * 2 + sub;
                uint32_t bbh[2] = { bh[sub*2], bh[sub*2+1] };
                uint32_t bbl[2] = { bl[sub*2], bl[sub*2+1] };
                mma_bf16(p[nt], aq_h, bbh);
                mma_bf16(p[nt], aq_h, bbl);
                mma_bf16(p[nt], aq_l, bbh);
            }
        }
    }

    // ---- mask + scale ----
    {
        int qg1 = q0 + mt * 16 + row_r;
        int qg2 = qg1 + 8;
        #pragma unroll
        for (int nt = 0; nt < 12; nt++) {
            int cb = k0 + half * 96 + nt * 8 + 2 * (lane & 3);
            #pragma unroll
            for (int e = 0; e < 4; e++) {
                int kg = cb + (e & 1);
                int qg = (e & 2) ? qg2 : qg1;
                bool valid = (kg >= 0) && (kg <= qg) && (kg >= qg - 128);
                p[nt][e] = valid ? p[nt][e] * ATT_SCALE : -1e30f;
            }
        }
    }

    // ---- softmax ----
    float inv1, inv2;
    {
        float m0v = -1e30f, m1v = -1e30f;
        #pragma unroll
        for (int nt = 0; nt < 12; nt++) {
            m0v = fmaxf(m0v, fmaxf(p[nt][0], p[nt][1]));
            m1v = fmaxf(m1v, fmaxf(p[nt][2], p[nt][3]));
        }
        m0v = fmaxf(m0v, __shfl_xor_sync(0xffffffffu, m0v, 1));
        m0v = fmaxf(m0v, __shfl_xor_sync(0xffffffffu, m0v, 2));
        m1v = fmaxf(m1v, __shfl_xor_sync(0xffffffffu, m1v, 1));
        m1v = fmaxf(m1v, __shfl_xor_sync(0xffffffffu, m1v, 2));
        if ((lane & 3) == 0) {
            redm[half * 64 + mt * 16 + row_r]     = m0v;
            redm[half * 64 + mt * 16 + row_r + 8] = m1v;
        }
        __syncthreads();
        float M0 = fmaxf(redm[mt*16 + row_r],     redm[64 + mt*16 + row_r]);
        float M1 = fmaxf(redm[mt*16 + row_r + 8], redm[64 + mt*16 + row_r + 8]);

        float s0 = 0.f, s1 = 0.f;
        #pragma unroll
        for (int nt = 0; nt < 12; nt++) {
            p[nt][0] = __expf(p[nt][0] - M0); s0 += p[nt][0];
            p[nt][1] = __expf(p[nt][1] - M0); s0 += p[nt][1];
            p[nt][2] = __expf(p[nt][2] - M1); s1 += p[nt][2];
            p[nt][3] = __expf(p[nt][3] - M1); s1 += p[nt][3];
        }
        s0 += __shfl_xor_sync(0xffffffffu, s0, 1);
        s0 += __shfl_xor_sync(0xffffffffu, s0, 2);
        s1 += __shfl_xor_sync(0xffffffffu, s1, 1);
        s1 += __shfl_xor_sync(0xffffffffu, s1, 2);
        if ((lane & 3) == 0) {
            reds[half * 64 + mt * 16 + row_r]     = s0;
            reds[half * 64 + mt * 16 + row_r + 8] = s1;
        }
        __syncthreads();
        inv1 = 1.0f / (reds[mt*16 + row_r]     + reds[64 + mt*16 + row_r]);
        inv2 = 1.0f / (reds[mt*16 + row_r + 8] + reds[64 + mt*16 + row_r + 8]);
    }

    // ---- O = P V (split, 3 passes, ldmatrix.trans on V) ----
    float o[8][4];
    #pragma unroll
    for (int nt = 0; nt < 8; nt++)
        #pragma unroll
        for (int e = 0; e < 4; e++) o[nt][e] = 0.f;

    const uint32_t vb_row = (uint32_t)(half * 96 + (lane & 7) + ((lane & 8) ? 8 : 0));
    const uint32_t vb_coff = (uint32_t)((lane & 16) ? 8 : 0);

    #pragma unroll
    for (int kt = 0; kt < 6; kt++) {
        uint32_t pah[4], pal[4];
        {
            float* e0 = p[2*kt]; float* e1 = p[2*kt+1];
            pah[0] = pk2(e0[0], e0[1]);
            pah[1] = pk2(e0[2], e0[3]);
            pah[2] = pk2(e1[0], e1[1]);
            pah[3] = pk2(e1[2], e1[3]);
            __nv_bfloat162* hp;
            float r0, r1;
            hp = (__nv_bfloat162*)&pah[0];
            r0 = e0[0] - __bfloat162float(hp->x); r1 = e0[1] - __bfloat162float(hp->y);
            pal[0] = pk2(r0, r1);
            hp = (__nv_bfloat162*)&pah[1];
            r0 = e0[2] - __bfloat162float(hp->x); r1 = e0[3] - __bfloat162float(hp->y);
            pal[1] = pk2(r0, r1);
            hp = (__nv_bfloat162*)&pah[2];
            r0 = e1[0] - __bfloat162float(hp->x); r1 = e1[1] - __bfloat162float(hp->y);
            pal[2] = pk2(r0, r1);
            hp = (__nv_bfloat162*)&pah[3];
            r0 = e1[2] - __bfloat162float(hp->x); r1 = e1[3] - __bfloat162float(hp->y);
            pal[3] = pk2(r0, r1);
        }
        #pragma unroll
        for (int dp = 0; dp < 4; dp++) {
            uint32_t addr = smb + AVH
                + ((vb_row + (uint32_t)(kt * 16)) * ARS + (uint32_t)(dp * 16) + vb_coff) * 2;
            uint32_t vh[4], vl[4];
            LDM_X4_T(vh[0], vh[1], vh[2], vh[3], addr);
            LDM_X4_T(vl[0], vl[1], vl[2], vl[3], addr + (AVL - AVH));
            #pragma unroll
            for (int sub = 0; sub < 2; sub++) {
                int nt = dp * 2 + sub;
                uint32_t bh2[2] = { vh[sub*2], vh[sub*2+1] };
                uint32_t bl2[2] = { vl[sub*2], vl[sub*2+1] };
                mma_bf16(o[nt], pah, bh2);
                mma_bf16(o[nt], pal, bh2);
                mma_bf16(o[nt], pah, bl2);
            }
        }
    }

    // ---- combine halves and write ----
    if (half == 1) {
        #pragma unroll
        for (int nt = 0; nt < 8; nt++) {
            int col = nt * 8 + 2 * (lane & 3);
            *(float2*)&scratch[mt * 1024 + row_r * 64 + col] =
                make_float2(o[nt][0], o[nt][1]);
            *(float2*)&scratch[mt * 1024 + (row_r + 8) * 64 + col] =
                make_float2(o[nt][2], o[nt][3]);
        }
    }
    __syncthreads();
    if (half == 0) {
        int r1g = q0 + mt * 16 + row_r;
        int r2g = r1g + 8;
        #pragma unroll
        for (int nt = 0; nt < 8; nt++) {
            int col = nt * 8 + 2 * (lane & 3);
            float2 s1v = *(float2*)&scratch[mt * 1024 + row_r * 64 + col];
            float2 s2v = *(float2*)&scratch[mt * 1024 + (row_r + 8) * 64 + col];
            float2 w1 = make_float2((o[nt][0] + s1v.x) * inv1, (o[nt][1] + s1v.y) * inv1);
            float2 w2 = make_float2((o[nt][2] + s2v.x) * inv2, (o[nt][3] + s2v.y) * inv2);
            *(float2*)(out + ((size_t)bb * T + r1g) * DIM + h * 64 + col) = w1;
            *(float2*)(out + ((size_t)bb * T + r2g) * DIM + h * 64 + col) = w2;
        }
    }
}

// ---------------------------------------------------------------------------
extern "C" void kernel_launch(void* const* d_in, const int* in_sizes, int n_in,
                              void* d_out, int out_size)
{
    const float* x    = (const float*)d_in[0];
    const float* rope = (const float*)d_in[2];
    const float* Wq   = (const float*)d_in[3];
    const float* Wk   = (const float*)d_in[4];
    const float* Wv   = (const float*)d_in[5];
    const float* Wo   = (const float*)d_in[6];
    float* out = (float*)d_out;

    float *q, *k, *v, *ao;
    __nv_bfloat16 *xhi, *xlo, *whi, *wlo;
    cudaGetSymbolAddress((void**)&q,   g_q);
    cudaGetSymbolAddress((void**)&k,   g_k);
    cudaGetSymbolAddress((void**)&v,   g_v);
    cudaGetSymbolAddress((void**)&ao,  g_ao);
    cudaGetSymbolAddress((void**)&xhi, g_xhi);
    cudaGetSymbolAddress((void**)&xlo, g_xlo);
    cudaGetSymbolAddress((void**)&whi, g_whi);
    cudaGetSymbolAddress((void**)&wlo, g_wlo);

    cudaFuncSetAttribute(gemm_mma, cudaFuncAttributeMaxDynamicSharedMemorySize, GEMM_SMEM);
    cudaFuncSetAttribute(attn_mma, cudaFuncAttributeMaxDynamicSharedMemorySize, ATT_SMEM);

    const int xn4 = M_TOTAL * DIM / 4;
    const int wn4 = DIM * DIM / 4;
    const size_t WSZ = (size_t)DIM * DIM;

    // splits
    split_bf16<<<xn4 / 256, 256>>>(x, xhi, xlo, xn4);
    split_bf16<<<wn4 / 256, 256>>>(Wq, whi + 0*WSZ, wlo + 0*WSZ, wn4);
    split_bf16<<<wn4 / 256, 256>>>(Wk, whi + 1*WSZ, wlo + 1*WSZ, wn4);
    split_bf16<<<wn4 / 256, 256>>>(Wv, whi + 2*WSZ, wlo + 2*WSZ, wn4);
    split_bf16<<<wn4 / 256, 256>>>(Wo, whi + 3*WSZ, wlo + 3*WSZ, wn4);

    // fused QKV GEMM (N = 3072)
    gemm_mma<<<dim3(24, 32), 256, GEMM_SMEM>>>(xhi, xlo, whi, wlo, q, k, v, 1);

    int nrope = B * H * T * 32;
    rope_kernel<<<(nrope + 255) / 256, 256>>>(q, k, rope);

    attn_mma<<<dim3(T / 64, H, B), 256, ATT_SMEM>>>(q, k, v, ao);

    split_bf16<<<xn4 / 256, 256>>>(ao, xhi, xlo, xn4);
    gemm_mma<<<dim3(8, 32), 256, GEMM_SMEM>>>(xhi, xlo, whi + 3*WSZ, wlo + 3*WSZ,
                                              out, out, out, 0);
}